// round 2
// baseline (speedup 1.0000x reference)
#include <cuda_runtime.h>
#include <math.h>
#include <stdint.h>

#define N_NODES 50000
#define E_EDGES 800000
#define E_TOT   (E_EDGES + N_NODES)
#define IN_CH 128
#define H1C 200
#define H2C 100
#define OUTC 2

// ---------------- scratch (static __device__, no allocs) ----------------
__device__ float g_h[(size_t)N_NODES * H1C];    // GEMM output per layer (max 200 ch)
__device__ float g_buf[(size_t)N_NODES * H1C];  // layer output / next GEMM input
__device__ float g_invn[N_NODES];
__device__ int   g_deg[N_NODES];
__device__ int   g_rowptr[N_NODES + 1];
__device__ int   g_cursor[N_NODES];
__device__ int   g_csrsrc[E_TOT];

// ---------------- Threefry-2x32 (matches JAX) ----------------
__host__ __device__ inline uint32_t rotl32(uint32_t v, int d) {
    return (v << d) | (v >> (32 - d));
}
__host__ __device__ inline void threefry2x32(uint32_t key0, uint32_t key1,
                                             uint32_t x0, uint32_t x1,
                                             uint32_t& o0, uint32_t& o1) {
    uint32_t ks[3] = {key0, key1, key0 ^ key1 ^ 0x1BD11BDAu};
    const int rot[8] = {13, 15, 26, 6, 17, 29, 16, 24};
    x0 += ks[0]; x1 += ks[1];
#pragma unroll
    for (int i = 0; i < 5; i++) {
        const int* r = &rot[(i & 1) * 4];
#pragma unroll
        for (int j = 0; j < 4; j++) { x0 += x1; x1 = rotl32(x1, r[j]); x1 ^= x0; }
        x0 += ks[(i + 1) % 3];
        x1 += ks[(i + 2) % 3] + (uint32_t)(i + 1);
    }
    o0 = x0; o1 = x1;
}

// ---------------- CSR build ----------------
__global__ void k_init() {
    int i = blockIdx.x * blockDim.x + threadIdx.x;
    if (i < N_NODES) { g_deg[i] = 1; g_cursor[i] = 0; }  // deg=1 accounts for self-loop
}

__global__ void k_count(const int* __restrict__ dst) {
    int e = blockIdx.x * blockDim.x + threadIdx.x;
    if (e < E_EDGES) atomicAdd(&g_deg[dst[e]], 1);
}

__global__ void k_scan() {  // single block, 1024 threads
    __shared__ int sh[1024];
    int tid = threadIdx.x;
    const int CH = (N_NODES + 1023) / 1024;  // 49
    int base = tid * CH;
    int s = 0;
    for (int i = 0; i < CH; i++) {
        int idx = base + i;
        if (idx < N_NODES) s += g_deg[idx];
    }
    sh[tid] = s;
    __syncthreads();
    for (int off = 1; off < 1024; off <<= 1) {
        int v = (tid >= off) ? sh[tid - off] : 0;
        __syncthreads();
        sh[tid] += v;
        __syncthreads();
    }
    int run = (tid == 0) ? 0 : sh[tid - 1];
    for (int i = 0; i < CH; i++) {
        int idx = base + i;
        if (idx < N_NODES) { g_rowptr[idx] = run; run += g_deg[idx]; }
    }
    if (tid == 1023) g_rowptr[N_NODES] = sh[1023];
}

__global__ void k_fill(const int* __restrict__ src, const int* __restrict__ dst) {
    int e = blockIdx.x * blockDim.x + threadIdx.x;
    if (e >= E_TOT) return;
    int s, d;
    if (e < E_EDGES) { s = src[e]; d = dst[e]; }
    else             { s = e - E_EDGES; d = s; }  // self-loop
    int pos = atomicAdd(&g_cursor[d], 1);
    g_csrsrc[g_rowptr[d] + pos] = s;
}

// ---------------- SGEMM (fp32, 64x64x16, 4x4 register tile) ----------------
// SRC: 0 = external A param, 1 = g_buf. Output always g_h.
template <int SRC>
__global__ void sgemm(const float* __restrict__ Aext, const float* __restrict__ B,
                      int M, int N, int K) {
    const float* A = (SRC == 0) ? Aext : g_buf;
    __shared__ __align__(16) float As[16][68];
    __shared__ __align__(16) float Bs[16][64];
    int tid = threadIdx.x;
    int tx = tid & 15, ty = tid >> 4;
    int rowBase = blockIdx.y * 64, colBase = blockIdx.x * 64;
    float acc[4][4] = {};
    for (int k0 = 0; k0 < K; k0 += 16) {
#pragma unroll
        for (int i = tid; i < 64 * 16; i += 256) {
            int r = i >> 4, c = i & 15;
            int gr = rowBase + r, gc = k0 + c;
            As[c][r] = (gr < M && gc < K) ? A[(size_t)gr * K + gc] : 0.0f;
        }
#pragma unroll
        for (int i = tid; i < 16 * 64; i += 256) {
            int r = i >> 6, c = i & 63;
            int gr = k0 + r, gc = colBase + c;
            Bs[r][c] = (gr < K && gc < N) ? B[(size_t)gr * N + gc] : 0.0f;
        }
        __syncthreads();
#pragma unroll
        for (int kk = 0; kk < 16; kk++) {
            float4 a4 = *reinterpret_cast<const float4*>(&As[kk][ty * 4]);
            float4 b4 = *reinterpret_cast<const float4*>(&Bs[kk][tx * 4]);
            float a[4] = {a4.x, a4.y, a4.z, a4.w};
            float b[4] = {b4.x, b4.y, b4.z, b4.w};
#pragma unroll
            for (int i = 0; i < 4; i++)
#pragma unroll
                for (int j = 0; j < 4; j++)
                    acc[i][j] += a[i] * b[j];
        }
        __syncthreads();
    }
#pragma unroll
    for (int i = 0; i < 4; i++) {
        int r = rowBase + ty * 4 + i;
        if (r >= M) continue;
#pragma unroll
        for (int j = 0; j < 4; j++) {
            int c = colBase + tx * 4 + j;
            if (c < N) g_h[(size_t)r * N + c] = acc[i][j];
        }
    }
}

// ---------------- row inverse-norm (reads g_h) ----------------
template <int D>
__global__ void k_norm() {
    int gw = (blockIdx.x * blockDim.x + threadIdx.x) >> 5;
    int lane = threadIdx.x & 31;
    if (gw >= N_NODES) return;
    float s = 0.0f;
    for (int d = lane; d < D; d += 32) {
        float v = g_h[(size_t)gw * D + d];
        s += v * v;
    }
#pragma unroll
    for (int o = 16; o; o >>= 1) s += __shfl_xor_sync(0xffffffffu, s, o);
    if (lane == 0) g_invn[gw] = 1.0f / fmaxf(sqrtf(s), 1e-12f);
}

// ---------------- fused attention + softmax + aggregate + relu (+dropout) ----
// One warp per destination node, online softmax over in-edges. Reads g_h.
// TO_OUT: write external out pointer (layer 3) vs g_buf.
template <int D, bool DROP, bool TO_OUT>
__global__ void k_node(const float* __restrict__ beta_p, float* __restrict__ outp,
                       uint32_t key0, uint32_t key1) {
    int v = (blockIdx.x * blockDim.x + threadIdx.x) >> 5;
    int lane = threadIdx.x & 31;
    if (v >= N_NODES) return;
    float* out = TO_OUT ? outp : g_buf;
    const float* h = g_h;
    constexpr int R = (D + 31) / 32;
    float hv[R];
#pragma unroll
    for (int j = 0; j < R; j++) {
        int d = lane + 32 * j;
        hv[j] = (d < D) ? h[(size_t)v * D + d] : 0.0f;
    }
    float invv = g_invn[v];
    float beta = *beta_p;
    int e0 = g_rowptr[v], e1 = g_rowptr[v + 1];
    float m = -INFINITY, denom = 0.0f;
    float acc[R];
#pragma unroll
    for (int j = 0; j < R; j++) acc[j] = 0.0f;

    for (int e = e0; e < e1; e++) {
        int s = g_csrsrc[e];
        float hs[R];
#pragma unroll
        for (int j = 0; j < R; j++) {
            int d = lane + 32 * j;
            hs[j] = (d < D) ? h[(size_t)s * D + d] : 0.0f;
        }
        float dot = 0.0f;
#pragma unroll
        for (int j = 0; j < R; j++) dot += hv[j] * hs[j];
#pragma unroll
        for (int o = 16; o; o >>= 1) dot += __shfl_xor_sync(0xffffffffu, dot, o);
        float a = beta * dot * invv * g_invn[s];
        float mn = fmaxf(m, a);
        float corr = expf(m - mn);   // m=-inf first iter -> corr=0
        float w = expf(a - mn);
        denom = denom * corr + w;
#pragma unroll
        for (int j = 0; j < R; j++) acc[j] = acc[j] * corr + w * hs[j];
        m = mn;
    }
    float dinv = 1.0f / fmaxf(denom, 1e-12f);
#pragma unroll
    for (int j = 0; j < R; j++) {
        int d = lane + 32 * j;
        if (d >= D) continue;
        float val = fmaxf(acc[j] * dinv, 0.0f);  // relu
        if (DROP) {
            uint32_t idx = (uint32_t)v * (uint32_t)D + (uint32_t)d;
            uint32_t b0, b1;
            threefry2x32(key0, key1, 0u, idx, b0, b1);  // partitionable: ctr=(hi=0, lo=idx)
            uint32_t bits = b0 ^ b1;
            float u = __uint_as_float((bits >> 9) | 0x3f800000u) - 1.0f;
            val = (u < 0.9f) ? (val / 0.9f) : 0.0f;
        }
        out[(size_t)v * D + d] = val;
    }
}

extern "C" void kernel_launch(void* const* d_in, const int* in_sizes, int n_in,
                              void* d_out, int out_size) {
    const float* x  = (const float*)d_in[0];
    const int*   ei = (const int*)d_in[1];
    const float* W1 = (const float*)d_in[2];
    const float* W2 = (const float*)d_in[3];
    const float* W3 = (const float*)d_in[4];
    const float* b1 = (const float*)d_in[5];
    const float* b2 = (const float*)d_in[6];
    const float* b3 = (const float*)d_in[7];
    float* out = (float*)d_out;
    const int* src = ei;
    const int* dst = ei + E_EDGES;

    // JAX keys: k1, k2 = split(key(42)); partitionable split:
    // new key i = threefry2x32(seed_key, ctr=(0, i))
    uint32_t k1a, k1b, k2a, k2b;
    threefry2x32(0u, 42u, 0u, 0u, k1a, k1b);
    threefry2x32(0u, 42u, 0u, 1u, k2a, k2b);

    // ---- CSR build (includes self-loops) ----
    k_init<<<(N_NODES + 255) / 256, 256>>>();
    k_count<<<(E_EDGES + 255) / 256, 256>>>(dst);
    k_scan<<<1, 1024>>>();
    k_fill<<<(E_TOT + 255) / 256, 256>>>(src, dst);

    const int warpGrid = (N_NODES * 32 + 255) / 256;

    // ---- layer 1: 128 -> 200 ----
    {
        dim3 g((H1C + 63) / 64, (N_NODES + 63) / 64);
        sgemm<0><<<g, 256>>>(x, W1, N_NODES, H1C, IN_CH);
        k_norm<H1C><<<warpGrid, 256>>>();
        k_node<H1C, true, false><<<warpGrid, 256>>>(b1, nullptr, k1a, k1b);
    }
    // ---- layer 2: 200 -> 100 ----
    {
        dim3 g((H2C + 63) / 64, (N_NODES + 63) / 64);
        sgemm<1><<<g, 256>>>(nullptr, W2, N_NODES, H2C, H1C);
        k_norm<H2C><<<warpGrid, 256>>>();
        k_node<H2C, true, false><<<warpGrid, 256>>>(b2, nullptr, k2a, k2b);
    }
    // ---- layer 3: 100 -> 2 (no dropout) ----
    {
        dim3 g((OUTC + 63) / 64, (N_NODES + 63) / 64);
        sgemm<1><<<g, 256>>>(nullptr, W3, N_NODES, OUTC, H2C);
        k_norm<OUTC><<<warpGrid, 256>>>();
        k_node<OUTC, false, true><<<warpGrid, 256>>>(b3, out, 0u, 0u);
    }
    (void)in_sizes; (void)n_in; (void)out_size;
}

// round 3
// speedup vs baseline: 1.5476x; 1.5476x over previous
#include <cuda_runtime.h>
#include <math.h>
#include <stdint.h>

#define N_NODES 50000
#define E_EDGES 800000
#define E_TOT   (E_EDGES + N_NODES)
#define IN_CH 128
#define H1C 200
#define H2C 100
#define OUTC 2

// ---------------- scratch (static __device__, no allocs) ----------------
__device__ float g_h[(size_t)N_NODES * H1C];    // GEMM output per layer (max 200 ch)
__device__ float g_buf[(size_t)N_NODES * H1C];  // layer output / next GEMM input
__device__ float g_invn[N_NODES];
__device__ int   g_deg[N_NODES];
__device__ int   g_rowptr[N_NODES + 1];
__device__ int   g_cursor[N_NODES];
__device__ int   g_csrsrc[E_TOT];

// ---------------- Threefry-2x32 (matches JAX, confirmed by rel_err 5e-7) ----
__host__ __device__ inline uint32_t rotl32(uint32_t v, int d) {
    return (v << d) | (v >> (32 - d));
}
__host__ __device__ inline void threefry2x32(uint32_t key0, uint32_t key1,
                                             uint32_t x0, uint32_t x1,
                                             uint32_t& o0, uint32_t& o1) {
    uint32_t ks[3] = {key0, key1, key0 ^ key1 ^ 0x1BD11BDAu};
    const int rot[8] = {13, 15, 26, 6, 17, 29, 16, 24};
    x0 += ks[0]; x1 += ks[1];
#pragma unroll
    for (int i = 0; i < 5; i++) {
        const int* r = &rot[(i & 1) * 4];
#pragma unroll
        for (int j = 0; j < 4; j++) { x0 += x1; x1 = rotl32(x1, r[j]); x1 ^= x0; }
        x0 += ks[(i + 1) % 3];
        x1 += ks[(i + 2) % 3] + (uint32_t)(i + 1);
    }
    o0 = x0; o1 = x1;
}

// ---------------- CSR build ----------------
__global__ void k_init() {
    int i = blockIdx.x * blockDim.x + threadIdx.x;
    if (i < N_NODES) { g_deg[i] = 1; g_cursor[i] = 0; }  // deg=1 => self-loop
}
__global__ void k_count(const int* __restrict__ dst) {
    int e = blockIdx.x * blockDim.x + threadIdx.x;
    if (e < E_EDGES) atomicAdd(&g_deg[dst[e]], 1);
}
__global__ void k_scan() {  // single block, 1024 threads
    __shared__ int sh[1024];
    int tid = threadIdx.x;
    const int CH = (N_NODES + 1023) / 1024;
    int base = tid * CH;
    int s = 0;
    for (int i = 0; i < CH; i++) {
        int idx = base + i;
        if (idx < N_NODES) s += g_deg[idx];
    }
    sh[tid] = s;
    __syncthreads();
    for (int off = 1; off < 1024; off <<= 1) {
        int v = (tid >= off) ? sh[tid - off] : 0;
        __syncthreads();
        sh[tid] += v;
        __syncthreads();
    }
    int run = (tid == 0) ? 0 : sh[tid - 1];
    for (int i = 0; i < CH; i++) {
        int idx = base + i;
        if (idx < N_NODES) { g_rowptr[idx] = run; run += g_deg[idx]; }
    }
    if (tid == 1023) g_rowptr[N_NODES] = sh[1023];
}
__global__ void k_fill(const int* __restrict__ src, const int* __restrict__ dst) {
    int e = blockIdx.x * blockDim.x + threadIdx.x;
    if (e >= E_TOT) return;
    int s, d;
    if (e < E_EDGES) { s = src[e]; d = dst[e]; }
    else             { s = e - E_EDGES; d = s; }
    int pos = atomicAdd(&g_cursor[d], 1);
    g_csrsrc[g_rowptr[d] + pos] = s;
}

// ---------------- SGEMM: 128x64x16 tiles, 8x4 microtile, double-buffered ----
// SRC: 0 = external A param, 1 = g_buf. Output always g_h. Requires K%4==0, N%4==0.
template <int SRC>
__global__ void __launch_bounds__(256) sgemm2(const float* __restrict__ Aext,
                                              const float* __restrict__ B,
                                              int M, int N, int K) {
    const float* A = (SRC == 0) ? Aext : g_buf;
    __shared__ __align__(16) float As[2][16][132];
    __shared__ __align__(16) float Bs[2][16][68];
    const int tid = threadIdx.x;
    const int tx = tid & 15, ty = tid >> 4;
    const int rowBase = blockIdx.y * 128, colBase = blockIdx.x * 64;

    const float4 z4 = make_float4(0.f, 0.f, 0.f, 0.f);
    float4 aP0, aP1, bP0;

    // global->regs for chunk at k0
    auto loadG = [&](int k0) {
        {
            int f = tid; int r = f >> 2, c4 = f & 3;
            int gr = rowBase + r, gc = k0 + c4 * 4;
            aP0 = (gr < M && gc < K) ? *reinterpret_cast<const float4*>(A + (size_t)gr * K + gc) : z4;
        }
        {
            int f = tid + 256; int r = f >> 2, c4 = f & 3;
            int gr = rowBase + r, gc = k0 + c4 * 4;
            aP1 = (gr < M && gc < K) ? *reinterpret_cast<const float4*>(A + (size_t)gr * K + gc) : z4;
        }
        {
            int r = tid >> 4, c = (tid & 15) * 4;
            int gr = k0 + r, gc = colBase + c;
            bP0 = (gr < K && gc < N) ? *reinterpret_cast<const float4*>(B + (size_t)gr * N + gc) : z4;
        }
    };
    auto storeS = [&](int buf) {
        {
            int f = tid; int r = f >> 2, c4 = (f & 3) * 4;
            As[buf][c4 + 0][r] = aP0.x; As[buf][c4 + 1][r] = aP0.y;
            As[buf][c4 + 2][r] = aP0.z; As[buf][c4 + 3][r] = aP0.w;
        }
        {
            int f = tid + 256; int r = f >> 2, c4 = (f & 3) * 4;
            As[buf][c4 + 0][r] = aP1.x; As[buf][c4 + 1][r] = aP1.y;
            As[buf][c4 + 2][r] = aP1.z; As[buf][c4 + 3][r] = aP1.w;
        }
        *reinterpret_cast<float4*>(&Bs[buf][tid >> 4][(tid & 15) * 4]) = bP0;
    };

    float acc[8][4];
#pragma unroll
    for (int i = 0; i < 8; i++)
#pragma unroll
        for (int j = 0; j < 4; j++) acc[i][j] = 0.f;

    const int nCh = (K + 15) / 16;
    loadG(0);
    storeS(0);
    __syncthreads();
    for (int ch = 0; ch < nCh; ch++) {
        int cur = ch & 1;
        if (ch + 1 < nCh) loadG((ch + 1) * 16);
#pragma unroll
        for (int kk = 0; kk < 16; kk++) {
            float4 a0 = *reinterpret_cast<const float4*>(&As[cur][kk][ty * 8]);
            float4 a1 = *reinterpret_cast<const float4*>(&As[cur][kk][ty * 8 + 4]);
            float4 b  = *reinterpret_cast<const float4*>(&Bs[cur][kk][tx * 4]);
            float av[8] = {a0.x, a0.y, a0.z, a0.w, a1.x, a1.y, a1.z, a1.w};
            float bv[4] = {b.x, b.y, b.z, b.w};
#pragma unroll
            for (int i = 0; i < 8; i++)
#pragma unroll
                for (int j = 0; j < 4; j++) acc[i][j] += av[i] * bv[j];
        }
        if (ch + 1 < nCh) { storeS(cur ^ 1); __syncthreads(); }
    }
#pragma unroll
    for (int i = 0; i < 8; i++) {
        int r = rowBase + ty * 8 + i;
        int c = colBase + tx * 4;
        if (r < M && c < N) {
            float4 o = make_float4(acc[i][0], acc[i][1], acc[i][2], acc[i][3]);
            *reinterpret_cast<float4*>(g_h + (size_t)r * N + c) = o;
        }
    }
}

// ---------------- row inverse-norm (reads g_h) ----------------
template <int D>
__global__ void k_norm() {
    int gw = (blockIdx.x * blockDim.x + threadIdx.x) >> 5;
    int lane = threadIdx.x & 31;
    if (gw >= N_NODES) return;
    float s = 0.0f;
    for (int d = lane; d < D; d += 32) {
        float v = g_h[(size_t)gw * D + d];
        s += v * v;
    }
#pragma unroll
    for (int o = 16; o; o >>= 1) s += __shfl_xor_sync(0xffffffffu, s, o);
    if (lane == 0) g_invn[gw] = 1.0f / fmaxf(sqrtf(s), 1e-12f);
}

// ---------------- fused attention + softmax + agg + relu + dropout ----------
// One warp per dst node, online softmax, software-pipelined edge loads.
template <int D, bool DROP>
__global__ void k_node(const float* __restrict__ beta_p, uint32_t key0, uint32_t key1) {
    int v = (blockIdx.x * blockDim.x + threadIdx.x) >> 5;
    int lane = threadIdx.x & 31;
    if (v >= N_NODES) return;
    const float* h = g_h;
    constexpr int R = (D + 31) / 32;
    float hv[R];
#pragma unroll
    for (int j = 0; j < R; j++) {
        int d = lane + 32 * j;
        hv[j] = (d < D) ? h[(size_t)v * D + d] : 0.0f;
    }
    float bi = __ldg(beta_p) * g_invn[v];
    int e0 = g_rowptr[v], e1 = g_rowptr[v + 1];
    float m = -1e30f, denom = 0.0f;
    float acc[R];
#pragma unroll
    for (int j = 0; j < R; j++) acc[j] = 0.0f;

    // prefetch first edge
    int s_n = g_csrsrc[e0];
    float hs_n[R], invs_n = g_invn[s_n];
#pragma unroll
    for (int j = 0; j < R; j++) {
        int d = lane + 32 * j;
        hs_n[j] = (d < D) ? h[(size_t)s_n * D + d] : 0.0f;
    }
    for (int e = e0; e < e1; e++) {
        float hs[R], invs = invs_n;
#pragma unroll
        for (int j = 0; j < R; j++) hs[j] = hs_n[j];
        if (e + 1 < e1) {  // issue next edge's loads before the exp chain
            s_n = g_csrsrc[e + 1];
            invs_n = g_invn[s_n];
#pragma unroll
            for (int j = 0; j < R; j++) {
                int d = lane + 32 * j;
                hs_n[j] = (d < D) ? h[(size_t)s_n * D + d] : 0.0f;
            }
        }
        float dot = 0.0f;
#pragma unroll
        for (int j = 0; j < R; j++) dot += hv[j] * hs[j];
#pragma unroll
        for (int o = 16; o; o >>= 1) dot += __shfl_xor_sync(0xffffffffu, dot, o);
        float a = bi * dot * invs;
        float mn = fmaxf(m, a);
        float corr = __expf(m - mn);
        float w = __expf(a - mn);
        denom = denom * corr + w;
#pragma unroll
        for (int j = 0; j < R; j++) acc[j] = acc[j] * corr + w * hs[j];
        m = mn;
    }
    float dinv = 1.0f / fmaxf(denom, 1e-12f);
#pragma unroll
    for (int j = 0; j < R; j++) {
        int d = lane + 32 * j;
        if (d >= D) continue;
        float val = fmaxf(acc[j] * dinv, 0.0f);
        if (DROP) {
            uint32_t idx = (uint32_t)v * (uint32_t)D + (uint32_t)d;
            uint32_t b0, b1;
            threefry2x32(key0, key1, 0u, idx, b0, b1);
            uint32_t bits = b0 ^ b1;
            float u = __uint_as_float((bits >> 9) | 0x3f800000u) - 1.0f;
            val = (u < 0.9f) ? (val / 0.9f) : 0.0f;
        }
        g_buf[(size_t)v * D + d] = val;
    }
}

// ---------------- layer 3 dedicated path (D=2) ----------------
// warp per node: h = g_buf[v,:100] @ W3[100,2], plus inverse norm. -> g_h[v*2..], g_invn[v]
__global__ void k_gemm3_norm(const float* __restrict__ W3) {
    int v = (blockIdx.x * blockDim.x + threadIdx.x) >> 5;
    int lane = threadIdx.x & 31;
    if (v >= N_NODES) return;
    float s0 = 0.f, s1 = 0.f;
#pragma unroll
    for (int j = 0; j < 4; j++) {
        int d = lane + 32 * j;
        if (d < H2C) {
            float hval = g_buf[(size_t)v * H2C + d];
            s0 += hval * __ldg(W3 + d * 2 + 0);
            s1 += hval * __ldg(W3 + d * 2 + 1);
        }
    }
#pragma unroll
    for (int o = 16; o; o >>= 1) {
        s0 += __shfl_xor_sync(0xffffffffu, s0, o);
        s1 += __shfl_xor_sync(0xffffffffu, s1, o);
    }
    if (lane == 0) {
        g_h[(size_t)v * 2 + 0] = s0;
        g_h[(size_t)v * 2 + 1] = s1;
        g_invn[v] = 1.0f / fmaxf(sqrtf(s0 * s0 + s1 * s1), 1e-12f);
    }
}

// thread per node: attention aggregate over D=2, relu, write external out.
__global__ void k_node3(const float* __restrict__ beta_p, float* __restrict__ out) {
    int v = blockIdx.x * blockDim.x + threadIdx.x;
    if (v >= N_NODES) return;
    const float2* h2 = reinterpret_cast<const float2*>(g_h);
    float2 hv = h2[v];
    float bi = __ldg(beta_p) * g_invn[v];
    int e0 = g_rowptr[v], e1 = g_rowptr[v + 1];
    float m = -1e30f, denom = 0.f, a0 = 0.f, a1 = 0.f;
    for (int e = e0; e < e1; e++) {
        int s = g_csrsrc[e];
        float2 hs = h2[s];
        float a = bi * (hv.x * hs.x + hv.y * hs.y) * g_invn[s];
        float mn = fmaxf(m, a);
        float corr = __expf(m - mn);
        float w = __expf(a - mn);
        denom = denom * corr + w;
        a0 = a0 * corr + w * hs.x;
        a1 = a1 * corr + w * hs.y;
        m = mn;
    }
    float dinv = 1.0f / fmaxf(denom, 1e-12f);
    out[(size_t)v * 2 + 0] = fmaxf(a0 * dinv, 0.f);
    out[(size_t)v * 2 + 1] = fmaxf(a1 * dinv, 0.f);
}

extern "C" void kernel_launch(void* const* d_in, const int* in_sizes, int n_in,
                              void* d_out, int out_size) {
    const float* x  = (const float*)d_in[0];
    const int*   ei = (const int*)d_in[1];
    const float* W1 = (const float*)d_in[2];
    const float* W2 = (const float*)d_in[3];
    const float* W3 = (const float*)d_in[4];
    const float* b1 = (const float*)d_in[5];
    const float* b2 = (const float*)d_in[6];
    const float* b3 = (const float*)d_in[7];
    float* out = (float*)d_out;
    const int* src = ei;
    const int* dst = ei + E_EDGES;

    uint32_t k1a, k1b, k2a, k2b;
    threefry2x32(0u, 42u, 0u, 0u, k1a, k1b);
    threefry2x32(0u, 42u, 0u, 1u, k2a, k2b);

    // ---- CSR build (includes self-loops) ----
    k_init<<<(N_NODES + 255) / 256, 256>>>();
    k_count<<<(E_EDGES + 255) / 256, 256>>>(dst);
    k_scan<<<1, 1024>>>();
    k_fill<<<(E_TOT + 255) / 256, 256>>>(src, dst);

    const int warpGrid = (N_NODES * 32 + 255) / 256;

    // ---- layer 1: 128 -> 200 ----
    {
        dim3 g((H1C + 63) / 64, (N_NODES + 127) / 128);
        sgemm2<0><<<g, 256>>>(x, W1, N_NODES, H1C, IN_CH);
        k_norm<H1C><<<warpGrid, 256>>>();
        k_node<H1C, true><<<warpGrid, 256>>>(b1, k1a, k1b);
    }
    // ---- layer 2: 200 -> 100 ----
    {
        dim3 g((H2C + 63) / 64, (N_NODES + 127) / 128);
        sgemm2<1><<<g, 256>>>(nullptr, W2, N_NODES, H2C, H1C);
        k_norm<H2C><<<warpGrid, 256>>>();
        k_node<H2C, true><<<warpGrid, 256>>>(b2, k2a, k2b);
    }
    // ---- layer 3: 100 -> 2 (no dropout), dedicated path ----
    {
        k_gemm3_norm<<<warpGrid, 256>>>(W3);
        k_node3<<<(N_NODES + 255) / 256, 256>>>(b3, out);
    }
    (void)in_sizes; (void)n_in; (void)out_size;
}

// round 4
// speedup vs baseline: 1.7424x; 1.1259x over previous
#include <cuda_runtime.h>
#include <math.h>
#include <stdint.h>

#define N_NODES 50000
#define E_EDGES 800000
#define E_TOT   (E_EDGES + N_NODES)
#define IN_CH 128
#define H1C 200
#define H2C 100
#define OUTC 2

// ---------------- scratch (static __device__, no allocs) ----------------
__device__ float g_h[(size_t)N_NODES * H1C];    // GEMM output per layer (max 200 ch)
__device__ float g_buf[(size_t)N_NODES * H1C];  // layer output / next GEMM input
__device__ float g_invn[N_NODES];
__device__ int   g_deg[N_NODES];
__device__ int   g_rowptr[N_NODES + 1];
__device__ int   g_cursor[N_NODES];
__device__ int   g_csrsrc[E_TOT];

// ---------------- Threefry-2x32 (matches JAX, confirmed) ----------------
__host__ __device__ inline uint32_t rotl32(uint32_t v, int d) {
    return (v << d) | (v >> (32 - d));
}
__host__ __device__ inline void threefry2x32(uint32_t key0, uint32_t key1,
                                             uint32_t x0, uint32_t x1,
                                             uint32_t& o0, uint32_t& o1) {
    uint32_t ks[3] = {key0, key1, key0 ^ key1 ^ 0x1BD11BDAu};
    const int rot[8] = {13, 15, 26, 6, 17, 29, 16, 24};
    x0 += ks[0]; x1 += ks[1];
#pragma unroll
    for (int i = 0; i < 5; i++) {
        const int* r = &rot[(i & 1) * 4];
#pragma unroll
        for (int j = 0; j < 4; j++) { x0 += x1; x1 = rotl32(x1, r[j]); x1 ^= x0; }
        x0 += ks[(i + 1) % 3];
        x1 += ks[(i + 2) % 3] + (uint32_t)(i + 1);
    }
    o0 = x0; o1 = x1;
}

// ---------------- CSR build ----------------
__global__ void k_init() {
    int i = blockIdx.x * blockDim.x + threadIdx.x;
    if (i < N_NODES) { g_deg[i] = 1; g_cursor[i] = 0; }  // deg=1 => self-loop
}
__global__ void k_count(const int* __restrict__ dst) {
    int e = blockIdx.x * blockDim.x + threadIdx.x;
    if (e < E_EDGES) atomicAdd(&g_deg[dst[e]], 1);
}
__global__ void k_scan() {  // single block, 1024 threads
    __shared__ int sh[1024];
    int tid = threadIdx.x;
    const int CH = (N_NODES + 1023) / 1024;
    int base = tid * CH;
    int s = 0;
    for (int i = 0; i < CH; i++) {
        int idx = base + i;
        if (idx < N_NODES) s += g_deg[idx];
    }
    sh[tid] = s;
    __syncthreads();
    for (int off = 1; off < 1024; off <<= 1) {
        int v = (tid >= off) ? sh[tid - off] : 0;
        __syncthreads();
        sh[tid] += v;
        __syncthreads();
    }
    int run = (tid == 0) ? 0 : sh[tid - 1];
    for (int i = 0; i < CH; i++) {
        int idx = base + i;
        if (idx < N_NODES) { g_rowptr[idx] = run; run += g_deg[idx]; }
    }
    if (tid == 1023) g_rowptr[N_NODES] = sh[1023];
}
__global__ void k_fill(const int* __restrict__ src, const int* __restrict__ dst) {
    int e = blockIdx.x * blockDim.x + threadIdx.x;
    if (e >= E_TOT) return;
    int s, d;
    if (e < E_EDGES) { s = src[e]; d = dst[e]; }
    else             { s = e - E_EDGES; d = s; }
    int pos = atomicAdd(&g_cursor[d], 1);
    g_csrsrc[g_rowptr[d] + pos] = s;
}

// ---------------- TF32 tensor-core GEMM ----------------
// C[M,N] = A[M,K] @ B[K,N], fp32 in/out, tf32 mma m16n8k8.
// Block tile 128x64x32, 8 warps (4m x 2n), warp tile 32x32 (2x4 mma tiles).
#define AS_STRIDE 36
#define BS_STRIDE 72

__device__ __forceinline__ uint32_t f2tf32(float f) {
    uint32_t o;
    asm volatile("cvt.rna.tf32.f32 %0, %1;" : "=r"(o) : "f"(f));
    return o;
}
__device__ __forceinline__ void mma_tf32(float* c, const uint32_t* a, const uint32_t* b) {
    asm volatile(
        "mma.sync.aligned.m16n8k8.row.col.f32.tf32.tf32.f32 "
        "{%0,%1,%2,%3}, {%4,%5,%6,%7}, {%8,%9}, {%0,%1,%2,%3};\n"
        : "+f"(c[0]), "+f"(c[1]), "+f"(c[2]), "+f"(c[3])
        : "r"(a[0]), "r"(a[1]), "r"(a[2]), "r"(a[3]), "r"(b[0]), "r"(b[1]));
}

// SRC: 0 = external A param, 1 = g_buf. Output always g_h.
template <int SRC>
__global__ void __launch_bounds__(256) gemm_tf32(const float* __restrict__ Aext,
                                                 const float* __restrict__ B,
                                                 int M, int N, int K) {
    const float* A = (SRC == 0) ? Aext : g_buf;
    __shared__ uint32_t As[128 * AS_STRIDE];  // [m][k] padded
    __shared__ uint32_t Bs[32 * BS_STRIDE];   // [k][n] padded
    const int tid = threadIdx.x;
    const int wid = tid >> 5, lane = tid & 31;
    const int g = lane >> 2, t = lane & 3;    // mma group / tid-in-group
    const int warpM = wid >> 1, warpN = wid & 1;
    const int rowBase = blockIdx.y * 128, colBase = blockIdx.x * 64;

    float acc[2][4][4];
#pragma unroll
    for (int mt = 0; mt < 2; mt++)
#pragma unroll
        for (int nt = 0; nt < 4; nt++)
#pragma unroll
            for (int r = 0; r < 4; r++) acc[mt][nt][r] = 0.f;

    const int nCh = (K + 31) / 32;
    for (int ch = 0; ch < nCh; ch++) {
        const int k0 = ch * 32;
        // ---- load A tile 128x32 (4 float4 per thread) ----
#pragma unroll
        for (int i = 0; i < 4; i++) {
            int f = tid + i * 256;
            int r = f >> 3, c4 = f & 7;         // 8 float4 per row
            int gr = rowBase + r, gk = k0 + c4 * 4;
            float4 v = make_float4(0.f, 0.f, 0.f, 0.f);
            if (gr < M && gk < K)               // K%4==0 -> float4 guard ok
                v = *reinterpret_cast<const float4*>(A + (size_t)gr * K + gk);
            uint4 u = make_uint4(f2tf32(v.x), f2tf32(v.y), f2tf32(v.z), f2tf32(v.w));
            *reinterpret_cast<uint4*>(&As[r * AS_STRIDE + c4 * 4]) = u;
        }
        // ---- load B tile 32x64 (2 float4 per thread) ----
#pragma unroll
        for (int i = 0; i < 2; i++) {
            int f = tid + i * 256;
            int r = f >> 4, c4 = f & 15;        // 16 float4 per row
            int gk = k0 + r, gn = colBase + c4 * 4;
            float4 v = make_float4(0.f, 0.f, 0.f, 0.f);
            if (gk < K && gn < N)               // N%4==0
                v = *reinterpret_cast<const float4*>(B + (size_t)gk * N + gn);
            uint4 u = make_uint4(f2tf32(v.x), f2tf32(v.y), f2tf32(v.z), f2tf32(v.w));
            *reinterpret_cast<uint4*>(&Bs[r * BS_STRIDE + c4 * 4]) = u;
        }
        __syncthreads();
        // ---- 4 k-steps of 8 ----
#pragma unroll
        for (int kk = 0; kk < 4; kk++) {
            const int kl = kk * 8;
            uint32_t afr[2][4];
#pragma unroll
            for (int mt = 0; mt < 2; mt++) {
                int m0 = warpM * 32 + mt * 16 + g;
                afr[mt][0] = As[m0 * AS_STRIDE + kl + t];
                afr[mt][1] = As[(m0 + 8) * AS_STRIDE + kl + t];
                afr[mt][2] = As[m0 * AS_STRIDE + kl + t + 4];
                afr[mt][3] = As[(m0 + 8) * AS_STRIDE + kl + t + 4];
            }
#pragma unroll
            for (int nt = 0; nt < 4; nt++) {
                int n0 = warpN * 32 + nt * 8 + g;
                uint32_t bfr[2];
                bfr[0] = Bs[(kl + t) * BS_STRIDE + n0];
                bfr[1] = Bs[(kl + t + 4) * BS_STRIDE + n0];
#pragma unroll
                for (int mt = 0; mt < 2; mt++) mma_tf32(acc[mt][nt], afr[mt], bfr);
            }
        }
        __syncthreads();
    }
    // ---- epilogue ----
#pragma unroll
    for (int mt = 0; mt < 2; mt++) {
#pragma unroll
        for (int nt = 0; nt < 4; nt++) {
            int n = colBase + warpN * 32 + nt * 8 + t * 2;
            if (n >= N) continue;
#pragma unroll
            for (int half = 0; half < 2; half++) {
                int m = rowBase + warpM * 32 + mt * 16 + g + half * 8;
                if (m < M) {
                    float2 o = make_float2(acc[mt][nt][half * 2], acc[mt][nt][half * 2 + 1]);
                    *reinterpret_cast<float2*>(g_h + (size_t)m * N + n) = o;
                }
            }
        }
    }
}

// ---------------- row inverse-norm (reads g_h) ----------------
template <int D>
__global__ void k_norm() {
    int gw = (blockIdx.x * blockDim.x + threadIdx.x) >> 5;
    int lane = threadIdx.x & 31;
    if (gw >= N_NODES) return;
    float s = 0.0f;
    for (int d = lane; d < D; d += 32) {
        float v = g_h[(size_t)gw * D + d];
        s += v * v;
    }
#pragma unroll
    for (int o = 16; o; o >>= 1) s += __shfl_xor_sync(0xffffffffu, s, o);
    if (lane == 0) g_invn[gw] = 1.0f / fmaxf(sqrtf(s), 1e-12f);
}

// ---------------- fused attention + softmax + agg + relu + dropout ----------
// One warp per dst node, online softmax, software-pipelined edge loads.
template <int D, bool DROP>
__global__ void k_node(const float* __restrict__ beta_p, uint32_t key0, uint32_t key1) {
    int v = (blockIdx.x * blockDim.x + threadIdx.x) >> 5;
    int lane = threadIdx.x & 31;
    if (v >= N_NODES) return;
    const float* h = g_h;
    constexpr int R = (D + 31) / 32;
    float hv[R];
#pragma unroll
    for (int j = 0; j < R; j++) {
        int d = lane + 32 * j;
        hv[j] = (d < D) ? h[(size_t)v * D + d] : 0.0f;
    }
    float bi = __ldg(beta_p) * g_invn[v];
    int e0 = g_rowptr[v], e1 = g_rowptr[v + 1];
    float m = -1e30f, denom = 0.0f;
    float acc[R];
#pragma unroll
    for (int j = 0; j < R; j++) acc[j] = 0.0f;

    int s_n = g_csrsrc[e0];
    float hs_n[R], invs_n = g_invn[s_n];
#pragma unroll
    for (int j = 0; j < R; j++) {
        int d = lane + 32 * j;
        hs_n[j] = (d < D) ? h[(size_t)s_n * D + d] : 0.0f;
    }
    for (int e = e0; e < e1; e++) {
        float hs[R], invs = invs_n;
#pragma unroll
        for (int j = 0; j < R; j++) hs[j] = hs_n[j];
        if (e + 1 < e1) {
            s_n = g_csrsrc[e + 1];
            invs_n = g_invn[s_n];
#pragma unroll
            for (int j = 0; j < R; j++) {
                int d = lane + 32 * j;
                hs_n[j] = (d < D) ? h[(size_t)s_n * D + d] : 0.0f;
            }
        }
        float dot = 0.0f;
#pragma unroll
        for (int j = 0; j < R; j++) dot += hv[j] * hs[j];
#pragma unroll
        for (int o = 16; o; o >>= 1) dot += __shfl_xor_sync(0xffffffffu, dot, o);
        float a = bi * dot * invs;
        float mn = fmaxf(m, a);
        float corr = __expf(m - mn);
        float w = __expf(a - mn);
        denom = denom * corr + w;
#pragma unroll
        for (int j = 0; j < R; j++) acc[j] = acc[j] * corr + w * hs[j];
        m = mn;
    }
    float dinv = 1.0f / fmaxf(denom, 1e-12f);
#pragma unroll
    for (int j = 0; j < R; j++) {
        int d = lane + 32 * j;
        if (d >= D) continue;
        float val = fmaxf(acc[j] * dinv, 0.0f);
        if (DROP) {
            uint32_t idx = (uint32_t)v * (uint32_t)D + (uint32_t)d;
            uint32_t b0, b1;
            threefry2x32(key0, key1, 0u, idx, b0, b1);
            uint32_t bits = b0 ^ b1;
            float u = __uint_as_float((bits >> 9) | 0x3f800000u) - 1.0f;
            val = (u < 0.9f) ? (val / 0.9f) : 0.0f;
        }
        g_buf[(size_t)v * D + d] = val;
    }
}

// ---------------- layer 3 dedicated path (D=2) ----------------
__global__ void k_gemm3_norm(const float* __restrict__ W3) {
    int v = (blockIdx.x * blockDim.x + threadIdx.x) >> 5;
    int lane = threadIdx.x & 31;
    if (v >= N_NODES) return;
    float s0 = 0.f, s1 = 0.f;
#pragma unroll
    for (int j = 0; j < 4; j++) {
        int d = lane + 32 * j;
        if (d < H2C) {
            float hval = g_buf[(size_t)v * H2C + d];
            s0 += hval * __ldg(W3 + d * 2 + 0);
            s1 += hval * __ldg(W3 + d * 2 + 1);
        }
    }
#pragma unroll
    for (int o = 16; o; o >>= 1) {
        s0 += __shfl_xor_sync(0xffffffffu, s0, o);
        s1 += __shfl_xor_sync(0xffffffffu, s1, o);
    }
    if (lane == 0) {
        g_h[(size_t)v * 2 + 0] = s0;
        g_h[(size_t)v * 2 + 1] = s1;
        g_invn[v] = 1.0f / fmaxf(sqrtf(s0 * s0 + s1 * s1), 1e-12f);
    }
}

__global__ void k_node3(const float* __restrict__ beta_p, float* __restrict__ out) {
    int v = blockIdx.x * blockDim.x + threadIdx.x;
    if (v >= N_NODES) return;
    const float2* h2 = reinterpret_cast<const float2*>(g_h);
    float2 hv = h2[v];
    float bi = __ldg(beta_p) * g_invn[v];
    int e0 = g_rowptr[v], e1 = g_rowptr[v + 1];
    float m = -1e30f, denom = 0.f, a0 = 0.f, a1 = 0.f;
    for (int e = e0; e < e1; e++) {
        int s = g_csrsrc[e];
        float2 hs = h2[s];
        float a = bi * (hv.x * hs.x + hv.y * hs.y) * g_invn[s];
        float mn = fmaxf(m, a);
        float corr = __expf(m - mn);
        float w = __expf(a - mn);
        denom = denom * corr + w;
        a0 = a0 * corr + w * hs.x;
        a1 = a1 * corr + w * hs.y;
        m = mn;
    }
    float dinv = 1.0f / fmaxf(denom, 1e-12f);
    out[(size_t)v * 2 + 0] = fmaxf(a0 * dinv, 0.f);
    out[(size_t)v * 2 + 1] = fmaxf(a1 * dinv, 0.f);
}

extern "C" void kernel_launch(void* const* d_in, const int* in_sizes, int n_in,
                              void* d_out, int out_size) {
    const float* x  = (const float*)d_in[0];
    const int*   ei = (const int*)d_in[1];
    const float* W1 = (const float*)d_in[2];
    const float* W2 = (const float*)d_in[3];
    const float* W3 = (const float*)d_in[4];
    const float* b1 = (const float*)d_in[5];
    const float* b2 = (const float*)d_in[6];
    const float* b3 = (const float*)d_in[7];
    float* out = (float*)d_out;
    const int* src = ei;
    const int* dst = ei + E_EDGES;

    uint32_t k1a, k1b, k2a, k2b;
    threefry2x32(0u, 42u, 0u, 0u, k1a, k1b);
    threefry2x32(0u, 42u, 0u, 1u, k2a, k2b);

    // ---- CSR build (includes self-loops) ----
    k_init<<<(N_NODES + 255) / 256, 256>>>();
    k_count<<<(E_EDGES + 255) / 256, 256>>>(dst);
    k_scan<<<1, 1024>>>();
    k_fill<<<(E_TOT + 255) / 256, 256>>>(src, dst);

    const int warpGrid = (N_NODES * 32 + 255) / 256;

    // ---- layer 1: 128 -> 200 ----
    {
        dim3 g((H1C + 63) / 64, (N_NODES + 127) / 128);
        gemm_tf32<0><<<g, 256>>>(x, W1, N_NODES, H1C, IN_CH);
        k_norm<H1C><<<warpGrid, 256>>>();
        k_node<H1C, true><<<warpGrid, 256>>>(b1, k1a, k1b);
    }
    // ---- layer 2: 200 -> 100 ----
    {
        dim3 g((H2C + 63) / 64, (N_NODES + 127) / 128);
        gemm_tf32<1><<<g, 256>>>(nullptr, W2, N_NODES, H2C, H1C);
        k_norm<H2C><<<warpGrid, 256>>>();
        k_node<H2C, true><<<warpGrid, 256>>>(b2, k2a, k2b);
    }
    // ---- layer 3: 100 -> 2 (no dropout), dedicated path ----
    {
        k_gemm3_norm<<<warpGrid, 256>>>(W3);
        k_node3<<<(N_NODES + 255) / 256, 256>>>(b3, out);
    }
    (void)in_sizes; (void)n_in; (void)out_size;
}